// round 2
// baseline (speedup 1.0000x reference)
#include <cuda_runtime.h>
#include <math.h>

#define B_  8
#define S_  1024
#define D_  1024
#define H_  16
#define DK_ 64
#define M_  (B_ * S_)   // 8192

// ---------------- scratch (static device allocations; no cudaMalloc) --------
__device__ float g_q[B_ * H_ * S_ * DK_];     // 32 MB, layout [B,H,S,DK]
__device__ float g_k[B_ * H_ * S_ * DK_];     // 32 MB
__device__ float g_v[B_ * H_ * S_ * DK_];     // 32 MB
__device__ float g_ctx[B_ * S_ * D_];         // 32 MB, layout [B,S,D]
__device__ float g_psum[B_ * 64];             // per-block partial sums (deterministic)
__device__ float g_psq[B_ * 64];

// ---------------------------------------------------------------------------
// QKV projection: C[m, n] = sum_k X[m,k] * W[h, k, j], n = h*64 + j
// 128x128x16 tiled SGEMM, 8x8 microtile, 256 threads. z selects wq/wk/wv.
// Output written in [B,H,S,DK] layout for the attention kernel.
// ---------------------------------------------------------------------------
__global__ __launch_bounds__(256) void qkv_kernel(
    const float* __restrict__ x, const float* __restrict__ wq,
    const float* __restrict__ wk, const float* __restrict__ wv)
{
    __shared__ float As[16][132];   // A transposed, padded
    __shared__ float Bs[16][132];

    const int zi = blockIdx.z;
    const float* W = (zi == 0) ? wq : (zi == 1) ? wk : wv;
    float* out = (zi == 0) ? g_q : (zi == 1) ? g_k : g_v;

    const int n0 = blockIdx.x * 128;
    const int m0 = blockIdx.y * 128;
    const int tid = threadIdx.x;
    const int tx = tid & 15, ty = tid >> 4;

    float acc[8][8] = {};

    for (int k0 = 0; k0 < D_; k0 += 16) {
        #pragma unroll
        for (int i = 0; i < 2; i++) {          // A tile: 128 x 16
            int f = tid + i * 256;
            int r = f >> 2, c4 = (f & 3) * 4;
            float4 v = *(const float4*)(x + (m0 + r) * D_ + k0 + c4);
            As[c4 + 0][r] = v.x; As[c4 + 1][r] = v.y;
            As[c4 + 2][r] = v.z; As[c4 + 3][r] = v.w;
        }
        #pragma unroll
        for (int i = 0; i < 2; i++) {          // B tile: 16 x 128 (per-head packed)
            int f = tid + i * 256;
            int r = f >> 5, c = (f & 31) * 4;
            int n = n0 + c;
            int h = n >> 6, j = n & 63;
            *(float4*)&Bs[r][c] =
                *(const float4*)(W + h * (D_ * DK_) + (k0 + r) * DK_ + j);
        }
        __syncthreads();
        #pragma unroll
        for (int kk = 0; kk < 16; kk++) {
            float a[8], b[8];
            *(float4*)&a[0] = *(const float4*)&As[kk][ty * 8];
            *(float4*)&a[4] = *(const float4*)&As[kk][ty * 8 + 4];
            *(float4*)&b[0] = *(const float4*)&Bs[kk][tx * 8];
            *(float4*)&b[4] = *(const float4*)&Bs[kk][tx * 8 + 4];
            #pragma unroll
            for (int ii = 0; ii < 8; ii++)
                #pragma unroll
                for (int jj = 0; jj < 8; jj++)
                    acc[ii][jj] += a[ii] * b[jj];
        }
        __syncthreads();
    }

    #pragma unroll
    for (int ii = 0; ii < 8; ii++) {
        int m = m0 + ty * 8 + ii;
        int b = m >> 10, s = m & 1023;
        #pragma unroll
        for (int j4 = 0; j4 < 2; j4++) {
            int n = n0 + tx * 8 + j4 * 4;
            int h = n >> 6, j = n & 63;
            float4 v = make_float4(acc[ii][j4 * 4 + 0], acc[ii][j4 * 4 + 1],
                                   acc[ii][j4 * 4 + 2], acc[ii][j4 * 4 + 3]);
            *(float4*)(out + ((b * H_ + h) * S_ + s) * DK_ + j) = v;
        }
    }
}

// ---------------------------------------------------------------------------
// Flash attention: one block = 64 query rows of one (b,h). Online softmax over
// 16 key tiles of 64. Smem exactly 48 KB: Qs + KP (K, then reused for P; skewed
// layout to avoid 16-way LDS conflicts without padding) + Vs.
// ---------------------------------------------------------------------------
__global__ __launch_bounds__(256) void attn_kernel(const int* __restrict__ mask)
{
    __shared__ float Qs[64 * 64];
    __shared__ float KP[64 * 64];   // skewed: idx(row, col) = row*64 + ((col + row) & 63)
    __shared__ float Vs[64 * 64];

    const int bh = blockIdx.y;          // 0..127
    const int b = bh >> 4;
    const int h = bh & 15;
    const int s0 = blockIdx.x * 64;
    const int tid = threadIdx.x;
    const int tx = tid & 15, ty = tid >> 4;
    const int r0 = ty * 4;              // this thread's query rows (local)
    const int c0 = tx * 4;              // this thread's key cols / dk cols (local)

    const float* qp = g_q + (bh * S_ + s0) * DK_;
    const float* kp = g_k + bh * S_ * DK_;
    const float* vp = g_v + bh * S_ * DK_;

    #pragma unroll
    for (int i = 0; i < 4; i++) {       // load Q tile (row-major)
        int f = tid + i * 256;
        int r = f >> 4, c = (f & 15) * 4;
        *(float4*)&Qs[r * 64 + c] = *(const float4*)(qp + r * 64 + c);
    }

    float mst[4], lst[4];
    float o[4][4] = {};
    #pragma unroll
    for (int i = 0; i < 4; i++) { mst[i] = -1e30f; lst[i] = 0.f; }

    for (int t0 = 0; t0 < S_; t0 += 64) {
        __syncthreads();                // prior-iter reads of KP/Vs done
        #pragma unroll
        for (int i = 0; i < 4; i++) {   // load K (skewed) + V (row-major)
            int f = tid + i * 256;
            int r = f >> 4, c = (f & 15) * 4;
            float4 kv = *(const float4*)(kp + (t0 + r) * DK_ + c);
            KP[r * 64 + ((c + 0 + r) & 63)] = kv.x;
            KP[r * 64 + ((c + 1 + r) & 63)] = kv.y;
            KP[r * 64 + ((c + 2 + r) & 63)] = kv.z;
            KP[r * 64 + ((c + 3 + r) & 63)] = kv.w;
            *(float4*)&Vs[r * 64 + c] = *(const float4*)(vp + (t0 + r) * DK_ + c);
        }
        __syncthreads();

        // ---- scores: acc = Q * K^T ----
        float acc[4][4] = {};
        #pragma unroll 16
        for (int k = 0; k < 64; k++) {
            float qv[4], kv[4];
            #pragma unroll
            for (int i = 0; i < 4; i++) qv[i] = Qs[(r0 + i) * 64 + k];
            #pragma unroll
            for (int j = 0; j < 4; j++) kv[j] = KP[(c0 + j) * 64 + ((k + c0 + j) & 63)];
            #pragma unroll
            for (int i = 0; i < 4; i++)
                #pragma unroll
                for (int j = 0; j < 4; j++)
                    acc[i][j] += qv[i] * kv[j];
        }

        // ---- scale + mask (matches: scale first, masked -> exactly -1e9) ----
        #pragma unroll
        for (int i = 0; i < 4; i++) {
            const int4 mv = *(const int4*)(mask + (b * S_ + (s0 + r0 + i)) * S_ + t0 + c0);
            acc[i][0] = mv.x ? acc[i][0] * 0.125f : -1e9f;
            acc[i][1] = mv.y ? acc[i][1] * 0.125f : -1e9f;
            acc[i][2] = mv.z ? acc[i][2] * 0.125f : -1e9f;
            acc[i][3] = mv.w ? acc[i][3] * 0.125f : -1e9f;
        }

        // ---- online softmax (row group = 16 contiguous lanes sharing ty) ----
        float alpha[4];
        #pragma unroll
        for (int i = 0; i < 4; i++) {
            float rm = fmaxf(fmaxf(acc[i][0], acc[i][1]), fmaxf(acc[i][2], acc[i][3]));
            #pragma unroll
            for (int w = 8; w > 0; w >>= 1)
                rm = fmaxf(rm, __shfl_xor_sync(0xffffffffu, rm, w));
            float mn = fmaxf(mst[i], rm);
            alpha[i] = __expf(mst[i] - mn);
            float rs = 0.f;
            #pragma unroll
            for (int j = 0; j < 4; j++) {
                acc[i][j] = __expf(acc[i][j] - mn);
                rs += acc[i][j];
            }
            #pragma unroll
            for (int w = 8; w > 0; w >>= 1)
                rs += __shfl_xor_sync(0xffffffffu, rs, w);
            lst[i] = lst[i] * alpha[i] + rs;
            mst[i] = mn;
        }

        __syncthreads();                // everyone done reading K from KP
        #pragma unroll
        for (int i = 0; i < 4; i++) {   // rescale O; write P into KP (skewed)
            o[i][0] *= alpha[i]; o[i][1] *= alpha[i];
            o[i][2] *= alpha[i]; o[i][3] *= alpha[i];
            #pragma unroll
            for (int j = 0; j < 4; j++)
                KP[(r0 + i) * 64 + ((c0 + j + r0 + i) & 63)] = acc[i][j];
        }
        __syncthreads();

        // ---- O += P @ V ----
        #pragma unroll 8
        for (int t = 0; t < 64; t++) {
            float pv[4];
            #pragma unroll
            for (int i = 0; i < 4; i++)
                pv[i] = KP[(r0 + i) * 64 + ((t + r0 + i) & 63)];
            float4 vv = *(const float4*)&Vs[t * 64 + c0];
            #pragma unroll
            for (int i = 0; i < 4; i++) {
                o[i][0] += pv[i] * vv.x;
                o[i][1] += pv[i] * vv.y;
                o[i][2] += pv[i] * vv.z;
                o[i][3] += pv[i] * vv.w;
            }
        }
    }

    #pragma unroll
    for (int i = 0; i < 4; i++) {       // ctx[b, s, h*64 + d]
        float inv = 1.f / lst[i];
        float4 v = make_float4(o[i][0] * inv, o[i][1] * inv,
                               o[i][2] * inv, o[i][3] * inv);
        *(float4*)(g_ctx + (b * S_ + (s0 + r0 + i)) * D_ + h * DK_ + c0) = v;
    }
}

// ---------------------------------------------------------------------------
// Output projection + residual + deterministic partial LN stats.
// res = ctx @ wo + x  -> d_out;  per-block (sum, sumsq) -> g_psum/g_psq.
// ---------------------------------------------------------------------------
__global__ __launch_bounds__(256) void proj_kernel(
    const float* __restrict__ wo, const float* __restrict__ x,
    float* __restrict__ out)
{
    __shared__ float As[16][132];
    __shared__ float Bs[16][132];
    __shared__ float red[2][8];

    const int n0 = blockIdx.x * 128;
    const int m0 = blockIdx.y * 128;
    const int tid = threadIdx.x;
    const int tx = tid & 15, ty = tid >> 4;

    float acc[8][8] = {};

    for (int k0 = 0; k0 < D_; k0 += 16) {
        #pragma unroll
        for (int i = 0; i < 2; i++) {
            int f = tid + i * 256;
            int r = f >> 2, c4 = (f & 3) * 4;
            float4 v = *(const float4*)(g_ctx + (m0 + r) * D_ + k0 + c4);
            As[c4 + 0][r] = v.x; As[c4 + 1][r] = v.y;
            As[c4 + 2][r] = v.z; As[c4 + 3][r] = v.w;
        }
        #pragma unroll
        for (int i = 0; i < 2; i++) {
            int f = tid + i * 256;
            int r = f >> 5, c = (f & 31) * 4;
            *(float4*)&Bs[r][c] = *(const float4*)(wo + (k0 + r) * D_ + n0 + c);
        }
        __syncthreads();
        #pragma unroll
        for (int kk = 0; kk < 16; kk++) {
            float a[8], b[8];
            *(float4*)&a[0] = *(const float4*)&As[kk][ty * 8];
            *(float4*)&a[4] = *(const float4*)&As[kk][ty * 8 + 4];
            *(float4*)&b[0] = *(const float4*)&Bs[kk][tx * 8];
            *(float4*)&b[4] = *(const float4*)&Bs[kk][tx * 8 + 4];
            #pragma unroll
            for (int ii = 0; ii < 8; ii++)
                #pragma unroll
                for (int jj = 0; jj < 8; jj++)
                    acc[ii][jj] += a[ii] * b[jj];
        }
        __syncthreads();
    }

    float lsum = 0.f, lsq = 0.f;
    #pragma unroll
    for (int ii = 0; ii < 8; ii++) {
        int m = m0 + ty * 8 + ii;
        #pragma unroll
        for (int j4 = 0; j4 < 2; j4++) {
            int n = n0 + tx * 8 + j4 * 4;
            float4 xv = *(const float4*)(x + m * D_ + n);
            float4 v;
            v.x = acc[ii][j4 * 4 + 0] + xv.x;
            v.y = acc[ii][j4 * 4 + 1] + xv.y;
            v.z = acc[ii][j4 * 4 + 2] + xv.z;
            v.w = acc[ii][j4 * 4 + 3] + xv.w;
            lsum += v.x + v.y + v.z + v.w;
            lsq  += v.x * v.x + v.y * v.y + v.z * v.z + v.w * v.w;
            *(float4*)(out + m * D_ + n) = v;
        }
    }

    #pragma unroll
    for (int w = 16; w > 0; w >>= 1) {
        lsum += __shfl_xor_sync(0xffffffffu, lsum, w);
        lsq  += __shfl_xor_sync(0xffffffffu, lsq, w);
    }
    int warp = tid >> 5, lane = tid & 31;
    if (lane == 0) { red[0][warp] = lsum; red[1][warp] = lsq; }
    __syncthreads();
    if (tid == 0) {
        float s = 0.f, q = 0.f;
        #pragma unroll
        for (int i = 0; i < 8; i++) { s += red[0][i]; q += red[1][i]; }
        int bb = m0 >> 10;                                  // batch of this m-tile
        int part = (blockIdx.y & 7) * 8 + blockIdx.x;       // 64 parts per batch
        g_psum[bb * 64 + part] = s;
        g_psq[bb * 64 + part]  = q;
    }
}

// ---------------------------------------------------------------------------
// LayerNorm over (S, D) per batch; stats from the 64 deterministic partials.
// ---------------------------------------------------------------------------
__global__ __launch_bounds__(256) void ln_kernel(float* __restrict__ out)
{
    const int blk = blockIdx.x;      // 2048 blocks x 4096 elems; 256 per batch
    const int b = blk >> 8;
    float s = 0.f, q = 0.f;
    #pragma unroll
    for (int i = 0; i < 64; i++) { s += g_psum[b * 64 + i]; q += g_psq[b * 64 + i]; }
    const float invN = 1.f / (float)(S_ * D_);
    const float mean = s * invN;
    const float var  = q * invN - mean * mean;
    const float rstd = rsqrtf(var + 1e-5f);

    float* p = out + (size_t)blk * 4096;
    #pragma unroll
    for (int i = 0; i < 4; i++) {
        float4 v = *(float4*)(p + (threadIdx.x + i * 256) * 4);
        v.x = (v.x - mean) * rstd; v.y = (v.y - mean) * rstd;
        v.z = (v.z - mean) * rstd; v.w = (v.w - mean) * rstd;
        *(float4*)(p + (threadIdx.x + i * 256) * 4) = v;
    }
}

// ---------------------------------------------------------------------------
extern "C" void kernel_launch(void* const* d_in, const int* in_sizes, int n_in,
                              void* d_out, int out_size)
{
    (void)in_sizes; (void)n_in; (void)out_size;
    const int*   mask = (const int*)  d_in[0];
    const float* x    = (const float*)d_in[1];
    const float* wq   = (const float*)d_in[2];
    const float* wk   = (const float*)d_in[3];
    const float* wv   = (const float*)d_in[4];
    const float* wo   = (const float*)d_in[5];
    float* out = (float*)d_out;

    qkv_kernel <<<dim3(D_ / 128, M_ / 128, 3), 256>>>(x, wq, wk, wv);
    attn_kernel<<<dim3(S_ / 64, B_ * H_),      256>>>(mask);
    proj_kernel<<<dim3(D_ / 128, M_ / 128),    256>>>(wo, x, out);
    ln_kernel  <<<dim3((B_ * S_ * D_) / 4096), 256>>>(out);
}